// round 6
// baseline (speedup 1.0000x reference)
// SampleScoreModel: softmax-weighted Gaussian-kernel score, fused persistent kernel.
// Round 6: 512 threads/CTA (32 warps/SM at 2 CTAs) to fix latency-boundness;
// per-thread tiles halved to fit 64 regs. Grid 256 = one wave -> epoch barrier safe.
#include <cuda_runtime.h>
#include <math.h>
#include <float.h>

#define B 32
#define D 64
#define NS 65536
#define TILE 256
#define GRID_MAIN (NS / TILE)   // 256
#define THREADS 512

#define ST_STRIDE 256
#define G_STRIDE 256
#define XS_STRIDE 36

// base column swizzle (bits2..4 ^= bits3..5); bijective per 32-block, keeps 4-float granules
#define SW(n) ((n) ^ ((((n) >> 3) & 7) << 2))

// smem layout (floats)
#define OFF_ST 0                         // 64*256 = 16384
#define OFF_G  16384                     // 32*256 = 8192 (combine buf reuses G..+10752)
#define OFF_XS 24576                     // 64*36  = 2304
#define OFF_Q  26880                     // 256
#define OFF_CB 27136                     // 32
#define OFF_MH 27168                     // 2*32
#define OFF_LH 27232                     // 2*32
#define SMEM_FLOATS 27296
#define SMEM_BYTES (SMEM_FLOATS * 4)     // 109,184 B -> 2 CTAs/SM

#define FMA2(acc, a, b) \
    asm("fma.rn.f32x2 %0, %1, %2, %0;" : "+l"(acc) : "l"(a), "l"(b))
#define DUP2(d, f) \
    asm("mov.b64 %0, {%1, %1};" : "=l"(d) : "r"(__float_as_uint(f)))

__device__ __forceinline__ float lo32(unsigned long long u) {
    return __uint_as_float((unsigned)u);
}
__device__ __forceinline__ float hi32(unsigned long long u) {
    return __uint_as_float((unsigned)(u >> 32));
}

__device__ float g_acc[GRID_MAIN][B][D];
__device__ float g_m[GRID_MAIN][B];
__device__ float g_l[GRID_MAIN][B];
__device__ unsigned int g_ctr;   // monotonic epoch counter (never reset; replay-safe)

__global__ __launch_bounds__(THREADS, 2)
void score_fused_kernel(const float* __restrict__ t,
                        const float* __restrict__ x,
                        const float* __restrict__ samples,
                        float* __restrict__ out) {
    extern __shared__ float sm[];
    float* st   = sm + OFF_ST;
    float* G    = sm + OFF_G;
    float* xs   = sm + OFF_XS;
    float* qn_s = sm + OFF_Q;
    float* cb_s = sm + OFF_CB;
    float* mh_s = sm + OFF_MH;   // [2][32] per-half maxes
    float* lh_s = sm + OFF_LH;   // [2][32] per-half sums

    const int tid = threadIdx.x;

    // ---- setup ----
#pragma unroll
    for (int i = tid; i < B * D; i += THREADS) {
        int b = i >> 6, k = i & 63;
        xs[k * XS_STRIDE + b] = x[i];
    }
    if (tid < B) {
        float sig = 0.01f * expf(t[tid] * 9.210340371976184f);
        cb_s[tid] = 0.5f / (sig * sig);
    }

    // ---- coalesced global load: flat float4 index = tid + 512*j ----
    const int d4 = tid & 15;       // float4 column
    const int nr = tid >> 4;       // 0..31
    const float4* sp = (const float4*)samples;
    const size_t base = (size_t)blockIdx.x * (TILE * (D / 4));
    float4 v[8];
#pragma unroll
    for (int j = 0; j < 8; j++) v[j] = sp[base + tid + 512 * j];

    // ---- transpose-store into st with d-dependent swizzle ----
    const int h4st = (d4 >> 1) << 2;
#pragma unroll
    for (int j = 0; j < 8; j++) {
        int n = nr + 32 * j;
        int pc = SW(n) ^ h4st;
        float* p = &st[(4 * d4) * ST_STRIDE + pc];
        p[0 * ST_STRIDE] = v[j].x;
        p[1 * ST_STRIDE] = v[j].y;
        p[2 * ST_STRIDE] = v[j].z;
        p[3 * ST_STRIDE] = v[j].w;
    }
    __syncthreads();

    // ---- q_n = ||s_n||^2, stored at SW(n) ----
    if (tid < TILE) {
        const int pn = SW(tid);
        float q = 0.0f;
#pragma unroll
        for (int k0 = 0; k0 < D; k0 += 8) {
            const int hk = (k0 >> 3) << 2;
            const float* col = &st[k0 * ST_STRIDE + (pn ^ hk)];
#pragma unroll
            for (int kk = 0; kk < 8; kk++) {
                float val = col[kk * ST_STRIDE];
                q = fmaf(val, val, q);
            }
        }
        qn_s[pn] = q;
    }
    __syncthreads();

    // ---- dot GEMM: 16 warps = 8 b-quads x 2 n-halves; thread = 4b x 4n ----
    const int w    = tid >> 5;
    const int lane = tid & 31;
    const int b0   = 4 * (w & 7);
    const int nh   = w >> 3;
    const int pnA  = SW(128 * nh + 4 * lane);

    float gvv[4][4];
    {
        unsigned long long dot2[4][2];
#pragma unroll
        for (int a = 0; a < 4; a++) { dot2[a][0] = 0ull; dot2[a][1] = 0ull; }

#pragma unroll 1
        for (int k0 = 0; k0 < D; k0 += 8) {
            const int hk = (k0 >> 3) << 2;
            const int pA = pnA ^ hk;
#pragma unroll
            for (int kk = 0; kk < 8; kk++) {
                const int k = k0 + kk;
                const float4 xv = *(const float4*)&xs[k * XS_STRIDE + b0];
                unsigned long long xd0, xd1, xd2, xd3;
                DUP2(xd0, xv.x); DUP2(xd1, xv.y); DUP2(xd2, xv.z); DUP2(xd3, xv.w);
                const ulonglong2 s01 = *(const ulonglong2*)&st[k * ST_STRIDE + pA];
                FMA2(dot2[0][0], xd0, s01.x); FMA2(dot2[0][1], xd0, s01.y);
                FMA2(dot2[1][0], xd1, s01.x); FMA2(dot2[1][1], xd1, s01.y);
                FMA2(dot2[2][0], xd2, s01.x); FMA2(dot2[2][1], xd2, s01.y);
                FMA2(dot2[3][0], xd3, s01.x); FMA2(dot2[3][1], xd3, s01.y);
            }
        }

        const float4 qq = *(const float4*)&qn_s[pnA];
#pragma unroll
        for (int a = 0; a < 4; a++) {
            const float c = cb_s[b0 + a];
            gvv[a][0] = c * (2.0f * lo32(dot2[a][0]) - qq.x);
            gvv[a][1] = c * (2.0f * hi32(dot2[a][0]) - qq.y);
            gvv[a][2] = c * (2.0f * lo32(dot2[a][1]) - qq.z);
            gvv[a][3] = c * (2.0f * hi32(dot2[a][1]) - qq.w);
            float m = fmaxf(fmaxf(gvv[a][0], gvv[a][1]), fmaxf(gvv[a][2], gvv[a][3]));
#pragma unroll
            for (int s = 16; s; s >>= 1) m = fmaxf(m, __shfl_xor_sync(0xffffffffu, m, s));
            if (lane == 0) mh_s[nh * 32 + b0 + a] = m;
        }
    }
    __syncthreads();   // both halves' maxes visible

    // ---- exp with full max; weights to G; per-half sums ----
#pragma unroll
    for (int a = 0; a < 4; a++) {
        const float mf = fmaxf(mh_s[b0 + a], mh_s[32 + b0 + a]);
        float p0 = __expf(gvv[a][0] - mf);
        float p1 = __expf(gvv[a][1] - mf);
        float p2 = __expf(gvv[a][2] - mf);
        float p3 = __expf(gvv[a][3] - mf);
        *(float4*)&G[(b0 + a) * G_STRIDE + pnA] = make_float4(p0, p1, p2, p3);
        float l = (p0 + p1) + (p2 + p3);
#pragma unroll
        for (int s = 16; s; s >>= 1) l += __shfl_xor_sync(0xffffffffu, l, s);
        if (lane == 0) lh_s[nh * 32 + b0 + a] = l;
    }
    __syncthreads();

    // ---- acc GEMM: thread = 2b x 8d, 4-way n-split of 64 ----
    const int cell = tid & 127;
    const int qg   = tid >> 7;       // n-split
    const int dg   = cell & 7;
    const int bgg  = cell >> 3;      // 0..15
    const int b0a  = 2 * bgg;
    const int d0   = 8 * dg;
    const int hd   = dg << 2;

    unsigned long long acc2[2][8];
#pragma unroll
    for (int a = 0; a < 2; a++)
#pragma unroll
        for (int r = 0; r < 8; r++) acc2[a][r] = 0ull;

    {
        const int nbase = 64 * qg;
#pragma unroll 2
        for (int n4 = 0; n4 < 64; n4 += 4) {
            const int pg = SW(nbase + n4);
            const int ps = pg ^ hd;
            const ulonglong2 p0 = *(const ulonglong2*)&G[(b0a    ) * G_STRIDE + pg];
            const ulonglong2 p1 = *(const ulonglong2*)&G[(b0a + 1) * G_STRIDE + pg];
#pragma unroll
            for (int r = 0; r < 8; r++) {
                const ulonglong2 sv = *(const ulonglong2*)&st[(d0 + r) * ST_STRIDE + ps];
                FMA2(acc2[0][r], p0.x, sv.x); FMA2(acc2[0][r], p0.y, sv.y);
                FMA2(acc2[1][r], p1.x, sv.x); FMA2(acc2[1][r], p1.y, sv.y);
            }
        }
    }

    float acc[2][8];
#pragma unroll
    for (int a = 0; a < 2; a++)
#pragma unroll
        for (int r = 0; r < 8; r++)
            acc[a][r] = lo32(acc2[a][r]) + hi32(acc2[a][r]);

    __syncthreads();            // done reading G/st; reuse as combine buffer

    // ---- combine 4 n-splits (stride-17 rows: bank-clean) ----
    float* buf = G;             // extends over xs/q dead space: 10752 floats >= 512*17
    {
        float* bp = &buf[tid * 17];
#pragma unroll
        for (int a = 0; a < 2; a++)
#pragma unroll
            for (int r = 0; r < 8; r++) bp[a * 8 + r] = acc[a][r];
    }
    __syncthreads();
    {
        const int cr = tid & 127;
        const int g  = tid >> 7;        // 0..3
        const int a  = g >> 1;
        const int r0 = 4 * (g & 1);
        float4 s4 = make_float4(0.f, 0.f, 0.f, 0.f);
#pragma unroll
        for (int q2 = 0; q2 < 4; q2++) {
            const float* bp = &buf[(q2 * 128 + cr) * 17 + a * 8 + r0];
            s4.x += bp[0]; s4.y += bp[1]; s4.z += bp[2]; s4.w += bp[3];
        }
        const int bglob = 2 * (cr >> 3) + a;
        const int dbase = 8 * (cr & 7) + r0;
        *(float4*)&g_acc[blockIdx.x][bglob][dbase] = s4;
    }
    if (tid < B) {
        g_m[blockIdx.x][tid] = fmaxf(mh_s[tid], mh_s[32 + tid]);
        g_l[blockIdx.x][tid] = lh_s[tid] + lh_s[32 + tid];
    }

    // ---- grid-wide epoch barrier (grid 256 <= 2*148 capacity: one wave, safe) ----
    {
        __shared__ unsigned s_target;
        if (tid == 0) {
            __threadfence();
            unsigned ticket = atomicAdd(&g_ctr, 1u);
            s_target = (ticket / GRID_MAIN + 1u) * GRID_MAIN;
        }
        __syncthreads();
        if (tid == 0) {
            const unsigned tgt = s_target;
            unsigned vseen;
            do {
                asm volatile("ld.acquire.gpu.global.u32 %0, [%1];"
                             : "=r"(vseen) : "l"(&g_ctr));
                if (vseen < tgt) __nanosleep(128);
            } while (vseen < tgt);
        }
        __syncthreads();
    }

    // ---- distributed reduction: CTA owns (b = blk&31, d-octet = blk>>5) ----
    {
        const int b   = blockIdx.x & 31;
        const int d0r = (blockIdx.x >> 5) * 8;
        float* red = sm;

        float mi = 0.0f;
        if (tid < GRID_MAIN) { mi = g_m[tid][b]; red[tid] = mi; }
        __syncthreads();
        if (tid < 32) {
            float m = red[tid];
#pragma unroll
            for (int k = 1; k < 8; k++) m = fmaxf(m, red[tid + 32 * k]);
#pragma unroll
            for (int s = 16; s; s >>= 1) m = fmaxf(m, __shfl_xor_sync(0xffffffffu, m, s));
            if (tid == 0) red[300] = m;
        }
        __syncthreads();
        const float M = red[300];

        float vals[9];
#pragma unroll
        for (int j = 0; j < 9; j++) vals[j] = 0.0f;
        if (tid < GRID_MAIN) {
            const float ei = __expf(mi - M);
            vals[0] = ei * g_l[tid][b];
            const float4 aA = *(const float4*)&g_acc[tid][b][d0r];
            const float4 aB = *(const float4*)&g_acc[tid][b][d0r + 4];
            vals[1] = ei * aA.x; vals[2] = ei * aA.y; vals[3] = ei * aA.z; vals[4] = ei * aA.w;
            vals[5] = ei * aB.x; vals[6] = ei * aB.y; vals[7] = ei * aB.z; vals[8] = ei * aB.w;
        }
#pragma unroll
        for (int s = 16; s; s >>= 1)
#pragma unroll
            for (int j = 0; j < 9; j++)
                vals[j] += __shfl_xor_sync(0xffffffffu, vals[j], s);
        if (tid < GRID_MAIN && (tid & 31) == 0) {
            const int w2 = tid >> 5;
#pragma unroll
            for (int j = 0; j < 9; j++) red[320 + w2 * 12 + j] = vals[j];
        }
        __syncthreads();
        if (tid < 8) {
            float L = 0.0f, A = 0.0f;
#pragma unroll
            for (int w3 = 0; w3 < 8; w3++) {
                L += red[320 + w3 * 12 + 0];
                A += red[320 + w3 * 12 + 1 + tid];
            }
            const float sig = 0.01f * expf(t[b] * 9.210340371976184f);
            out[b * D + d0r + tid] = (1.0f / sig) * (A / L - x[b * D + d0r + tid]);
        }
    }
}

extern "C" void kernel_launch(void* const* d_in, const int* in_sizes, int n_in,
                              void* d_out, int out_size) {
    const float* t = nullptr;
    const float* x = nullptr;
    const float* s = nullptr;
    for (int i = 0; i < n_in; i++) {
        if      (in_sizes[i] == B)      t = (const float*)d_in[i];
        else if (in_sizes[i] == B * D)  x = (const float*)d_in[i];
        else if (in_sizes[i] == NS * D) s = (const float*)d_in[i];
    }
    cudaFuncSetAttribute(score_fused_kernel,
                         cudaFuncAttributeMaxDynamicSharedMemorySize, SMEM_BYTES);
    score_fused_kernel<<<GRID_MAIN, THREADS, SMEM_BYTES>>>(t, x, s, (float*)d_out);
}